// round 4
// baseline (speedup 1.0000x reference)
#include <cuda_runtime.h>

#define N3 262144
#define N2 65536
#define N1 16384

typedef unsigned long long ull;

// ---------------- scratch (device globals; no allocations allowed) ----------
__device__ float g_x8   [N3 * 16];
__device__ float g_x7p  [N2 * 16];
__device__ float g_x7   [N2 * 32];
__device__ float g_x6p  [N1 * 32];
__device__ float g_x6   [N1 * 64];
__device__ float g_x7dec[N2 * 32];
__device__ float g_x8dec[N3 * 16];
__device__ int   g_pidx3[N3];
__device__ int   g_pidx2[N2];

// ---------------- packed f32x2 helpers ---------------------------------------
__device__ __forceinline__ ull pack2(float lo, float hi) {
    ull r;
    asm("mov.b64 %0, {%1, %2};" : "=l"(r) : "f"(lo), "f"(hi));
    return r;
}
__device__ __forceinline__ ull bcast2(float v) {
    ull r;
    asm("mov.b64 %0, {%1, %1};" : "=l"(r) : "f"(v));
    return r;
}
__device__ __forceinline__ void ffma2(ull& d, ull a, ull b) {
    asm("fma.rn.f32x2 %0, %1, %2, %0;" : "+l"(d) : "l"(a), "l"(b));
}
__device__ __forceinline__ float2 unpack2(ull v) {
    float2 r;
    asm("mov.b64 {%0, %1}, %2;" : "=f"(r.x), "=f"(r.y) : "l"(v));
    return r;
}

// ---------------- fused prep: pidx3, pidx2, zero x7p, zero x6p ---------------
__device__ __forceinline__ int lower_bound_shift(const int* __restrict__ keys,
                                                 int Np, int v) {
    int lo = 0, hi = Np;
    while (lo < hi) {
        int mid = (lo + hi) >> 1;
        if (keys[mid] < v) lo = mid + 1; else hi = mid;
    }
    return lo;
}

__global__ void prep_kernel(const int* __restrict__ keys3,
                            const int* __restrict__ keys2,
                            const int* __restrict__ keys1,
                            int* __restrict__ pidx3, int* __restrict__ pidx2,
                            float* __restrict__ x7p, float* __restrict__ x6p) {
    const int T0 = N3;                  // pidx3
    const int T1 = T0 + N2;             // pidx2
    const int T2 = T1 + N2 * 16;        // zero x7p
    const int T3 = T2 + N1 * 32;        // zero x6p
    int i = blockIdx.x * blockDim.x + threadIdx.x;
    int stride = gridDim.x * blockDim.x;
    for (; i < T3; i += stride) {
        if (i < T0) {
            pidx3[i] = lower_bound_shift(keys2, N2, keys3[i] >> 2);
        } else if (i < T1) {
            int k = i - T0;
            pidx2[k] = lower_bound_shift(keys1, N1, keys2[k] >> 2);
        } else if (i < T2) {
            x7p[i - T1] = 0.0f;
        } else {
            x6p[i - T2] = 0.0f;
        }
    }
}

// segment-max pool. Post-ReLU values >= 0, so int-bit atomicMax == float max
// and 0-init matches the reference's (-inf -> 0) fill.
template <int C>
__global__ void pool_kernel(const float* __restrict__ child,
                            const int* __restrict__ pidx,
                            int Nc, int Np, float* __restrict__ parent) {
    int i = blockIdx.x * blockDim.x + threadIdx.x;
    if (i >= Nc * C) return;
    int node = i / C;
    int c = i - node * C;
    int p = pidx[node];
    if (p < Np) {
        float v = child[i];
        atomicMax(reinterpret_cast<int*>(&parent[(size_t)p * C + c]),
                  __float_as_int(v));
    }
}

// ---------------- fused gather + (9*CIN -> COB) conv, packed f32x2 -----------
// Weight slab staged once in shared as [j][c][o] (o contiguous) so one LDS.128
// yields two packed output-pairs. Accumulators are packed f32x2 -> 2 lane-FMAs
// per FFMA-pipe issue slot. NPN nodes/thread amortize the broadcast LDS.
// INDIRECT fuses the unpool gather (feat row = clamp(pidx[idx])).
template <int CIN, int COB, int NPN, bool RELU, bool INDIRECT>
__global__ void __launch_bounds__(128)
conv_kernel(const float* __restrict__ feat, const int* __restrict__ neigh,
            const int* __restrict__ pidx, int Nfeat, int ostride,
            const float* __restrict__ w, const float* __restrict__ b,
            float* __restrict__ out) {
    __shared__ __align__(16) float ws[9 * CIN * COB];
    const int tid = threadIdx.x;
    const int oc_base = blockIdx.y * COB;
    const int cin9 = 9 * CIN;

    // stage slab: ws[(j*CIN + c)*COB + o] = w[oc_base+o][j*CIN + c]
    for (int s = tid; s < COB * cin9; s += 128) {
        int o = s / cin9;
        int rem = s - o * cin9;        // j*CIN + c
        ws[rem * COB + o] = w[(size_t)(oc_base + o) * cin9 + rem];
    }
    __syncthreads();

    int node[NPN];
    int idx[NPN][9];
#pragma unroll
    for (int t = 0; t < NPN; t++) {
        node[t] = blockIdx.x * (128 * NPN) + t * 128 + tid;
#pragma unroll
        for (int j = 0; j < 9; j++) idx[t][j] = neigh[(size_t)node[t] * 9 + j];
        if (INDIRECT) {
#pragma unroll
            for (int j = 0; j < 9; j++) {
                if (idx[t][j] >= 0) {
                    int p = pidx[idx[t][j]];
                    idx[t][j] = p < Nfeat ? p : Nfeat - 1;
                }
            }
        }
    }

    if constexpr (COB == 1) {
        // tiny head layer: scalar path
        float acc[NPN];
#pragma unroll
        for (int t = 0; t < NPN; t++) acc[t] = b[oc_base];
        for (int j = 0; j < 9; j++) {
#pragma unroll
            for (int c4 = 0; c4 < CIN; c4 += 4) {
                float4 wv = *reinterpret_cast<const float4*>(&ws[j * CIN + c4]);
#pragma unroll
                for (int t = 0; t < NPN; t++) {
                    float4 f = (idx[t][j] >= 0)
                        ? *reinterpret_cast<const float4*>(
                              &feat[(size_t)idx[t][j] * CIN + c4])
                        : make_float4(0.f, 0.f, 0.f, 0.f);
                    acc[t] += f.x * wv.x + f.y * wv.y + f.z * wv.z + f.w * wv.w;
                }
            }
        }
#pragma unroll
        for (int t = 0; t < NPN; t++)
            out[(size_t)node[t] * ostride + oc_base] =
                RELU ? fmaxf(acc[t], 0.f) : acc[t];
    } else {
        ull acc2[NPN][COB / 2];
#pragma unroll
        for (int o = 0; o < COB; o += 2) {
            ull bv = pack2(b[oc_base + o], b[oc_base + o + 1]);
#pragma unroll
            for (int t = 0; t < NPN; t++) acc2[t][o / 2] = bv;
        }

        if constexpr (CIN == 1) {
#pragma unroll
            for (int j = 0; j < 9; j++) {
                ull ff[NPN];
#pragma unroll
                for (int t = 0; t < NPN; t++)
                    ff[t] = bcast2((idx[t][j] >= 0) ? __ldg(&feat[idx[t][j]])
                                                    : 0.f);
#pragma unroll
                for (int og = 0; og < COB; og += 4) {
                    ulonglong2 wl =
                        *reinterpret_cast<const ulonglong2*>(&ws[j * COB + og]);
#pragma unroll
                    for (int t = 0; t < NPN; t++) {
                        ffma2(acc2[t][og / 2], ff[t], wl.x);
                        ffma2(acc2[t][og / 2 + 1], ff[t], wl.y);
                    }
                }
            }
        } else {
            for (int j = 0; j < 9; j++) {
#pragma unroll 2
                for (int c4 = 0; c4 < CIN; c4 += 4) {
                    float4 f[NPN];
#pragma unroll
                    for (int t = 0; t < NPN; t++) {
                        if (idx[t][j] >= 0)
                            f[t] = *reinterpret_cast<const float4*>(
                                &feat[(size_t)idx[t][j] * CIN + c4]);
                        else
                            f[t] = make_float4(0.f, 0.f, 0.f, 0.f);
                    }
#pragma unroll
                    for (int c = 0; c < 4; c++) {
                        ull ff[NPN];
#pragma unroll
                        for (int t = 0; t < NPN; t++) {
                            float fv = c == 0 ? f[t].x : c == 1 ? f[t].y
                                     : c == 2 ? f[t].z : f[t].w;
                            ff[t] = bcast2(fv);
                        }
                        const float* wrow = &ws[(j * CIN + c4 + c) * COB];
#pragma unroll
                        for (int og = 0; og < COB; og += 4) {
                            ulonglong2 wl =
                                *reinterpret_cast<const ulonglong2*>(&wrow[og]);
#pragma unroll
                            for (int t = 0; t < NPN; t++) {
                                ffma2(acc2[t][og / 2], ff[t], wl.x);
                                ffma2(acc2[t][og / 2 + 1], ff[t], wl.y);
                            }
                        }
                    }
                }
            }
        }

#pragma unroll
        for (int t = 0; t < NPN; t++) {
            float* orow = out + (size_t)node[t] * ostride + oc_base;
#pragma unroll
            for (int o = 0; o < COB; o += 4) {
                float2 p0 = unpack2(acc2[t][o / 2]);
                float2 p1 = unpack2(acc2[t][o / 2 + 1]);
                float4 v;
                v.x = RELU ? fmaxf(p0.x, 0.f) : p0.x;
                v.y = RELU ? fmaxf(p0.y, 0.f) : p0.y;
                v.z = RELU ? fmaxf(p1.x, 0.f) : p1.x;
                v.w = RELU ? fmaxf(p1.y, 0.f) : p1.y;
                *reinterpret_cast<float4*>(orow + o) = v;
            }
        }
    }
}

// ---------------- launch ------------------------------------------------------
static inline int cdiv(int a, int b) { return (a + b - 1) / b; }

extern "C" void kernel_launch(void* const* d_in, const int* in_sizes, int n_in,
                              void* d_out, int out_size) {
    const float* features = (const float*)d_in[0];
    const int* keys3   = (const int*)d_in[1];
    const int* keys2   = (const int*)d_in[2];
    const int* keys1   = (const int*)d_in[3];
    const int* neighs3 = (const int*)d_in[4];
    const int* neighs2 = (const int*)d_in[5];
    const int* neighs1 = (const int*)d_in[6];
    const float* w_enc1 = (const float*)d_in[7];
    const float* b_enc1 = (const float*)d_in[8];
    const float* w_enc2 = (const float*)d_in[9];
    const float* b_enc2 = (const float*)d_in[10];
    const float* w_enc3 = (const float*)d_in[11];
    const float* b_enc3 = (const float*)d_in[12];
    const float* w_dec1 = (const float*)d_in[13];
    const float* b_dec1 = (const float*)d_in[14];
    const float* w_dec2 = (const float*)d_in[15];
    const float* b_dec2 = (const float*)d_in[16];
    const float* w_head = (const float*)d_in[17];
    const float* b_head = (const float*)d_in[18];
    float* out = (float*)d_out;

    float *x8, *x7p, *x7, *x6p, *x6, *x7dec, *x8dec;
    int *pidx3, *pidx2;
    cudaGetSymbolAddress((void**)&x8, g_x8);
    cudaGetSymbolAddress((void**)&x7p, g_x7p);
    cudaGetSymbolAddress((void**)&x7, g_x7);
    cudaGetSymbolAddress((void**)&x6p, g_x6p);
    cudaGetSymbolAddress((void**)&x6, g_x6);
    cudaGetSymbolAddress((void**)&x7dec, g_x7dec);
    cudaGetSymbolAddress((void**)&x8dec, g_x8dec);
    cudaGetSymbolAddress((void**)&pidx3, g_pidx3);
    cudaGetSymbolAddress((void**)&pidx2, g_pidx2);

    // launch 0: fused prep (pidx3, pidx2, zero pool accumulators)
    prep_kernel<<<2048, 256>>>(keys3, keys2, keys1, pidx3, pidx2, x7p, x6p);

    // 1: enc1 [N3,1]->[N3,16]
    conv_kernel<1, 16, 4, true, false><<<dim3(N3 / 512, 1), 128>>>(
        features, neighs3, nullptr, N3, 16, w_enc1, b_enc1, x8);
    // 2: pool 3->2
    pool_kernel<16><<<cdiv(N3 * 16, 256), 256>>>(x8, pidx3, N3, N2, x7p);
    // 3: enc2 [N2,16]->[N2,32]  (COB 16, y=2)
    conv_kernel<16, 16, 2, true, false><<<dim3(N2 / 256, 2), 128>>>(
        x7p, neighs2, nullptr, N2, 32, w_enc2, b_enc2, x7);
    // 4: pool 2->1
    pool_kernel<32><<<cdiv(N2 * 32, 256), 256>>>(x7, pidx2, N2, N1, x6p);
    // 5: enc3 [N1,32]->[N1,64]  (COB 16, y=4, NPN=1 for occupancy)
    conv_kernel<32, 16, 1, true, false><<<dim3(N1 / 128, 4), 128>>>(
        x6p, neighs1, nullptr, N1, 64, w_enc3, b_enc3, x6);
    // 6: dec1 (unpool 1->2 fused) [N2,9*64]->[N2,32]  (COB 16, y=2)
    conv_kernel<64, 16, 2, true, true><<<dim3(N2 / 256, 2), 128>>>(
        x6, neighs2, pidx2, N1, 32, w_dec1, b_dec1, x7dec);
    // 7: dec2 (unpool 2->3 fused) [N3,9*32]->[N3,16]
    conv_kernel<32, 16, 2, true, true><<<dim3(N3 / 256, 1), 128>>>(
        x7dec, neighs3, pidx3, N2, 16, w_dec2, b_dec2, x8dec);
    // 8: head [N3,16]->[N3,1], no relu
    conv_kernel<16, 1, 4, false, false><<<dim3(N3 / 512, 1), 128>>>(
        x8dec, neighs3, nullptr, N3, 1, w_head, b_head, out);
}

// round 6
// speedup vs baseline: 1.6026x; 1.6026x over previous
#include <cuda_runtime.h>

#define N3 262144
#define N2 65536
#define N1 16384

typedef unsigned long long ull;

// ---------------- scratch (device globals; no allocations allowed) ----------
__device__ float g_x8   [N3 * 16];
__device__ float g_x7p  [N2 * 16];
__device__ float g_x7   [N2 * 32];
__device__ float g_x6p  [N1 * 32];
__device__ float g_x6   [N1 * 64];
__device__ float g_x7dec[N2 * 32];
__device__ float g_x8dec[N3 * 16];
__device__ int   g_pidx3[N3];
__device__ int   g_pidx2[N2];

// ---------------- packed f32x2 helpers ---------------------------------------
__device__ __forceinline__ ull pack2(float lo, float hi) {
    ull r;
    asm("mov.b64 %0, {%1, %2};" : "=l"(r) : "f"(lo), "f"(hi));
    return r;
}
__device__ __forceinline__ ull bcast2(float v) {
    ull r;
    asm("mov.b64 %0, {%1, %1};" : "=l"(r) : "f"(v));
    return r;
}
__device__ __forceinline__ void ffma2(ull& d, ull a, ull b) {
    asm("fma.rn.f32x2 %0, %1, %2, %0;" : "+l"(d) : "l"(a), "l"(b));
}
__device__ __forceinline__ float2 unpack2(ull v) {
    float2 r;
    asm("mov.b64 {%0, %1}, %2;" : "=f"(r.x), "=f"(r.y) : "l"(v));
    return r;
}

// ---------------- fused prep: pidx3, pidx2, zero x7p, zero x6p ---------------
__device__ __forceinline__ int lower_bound_shift(const int* __restrict__ keys,
                                                 int Np, int v) {
    int lo = 0, hi = Np;
    while (lo < hi) {
        int mid = (lo + hi) >> 1;
        if (keys[mid] < v) lo = mid + 1; else hi = mid;
    }
    return lo;
}

__global__ void prep_kernel(const int* __restrict__ keys3,
                            const int* __restrict__ keys2,
                            const int* __restrict__ keys1,
                            int* __restrict__ pidx3, int* __restrict__ pidx2,
                            float* __restrict__ x7p, float* __restrict__ x6p) {
    const int T0 = N3;
    const int T1 = T0 + N2;
    const int T2 = T1 + N2 * 16;
    const int T3 = T2 + N1 * 32;
    int i = blockIdx.x * blockDim.x + threadIdx.x;
    int stride = gridDim.x * blockDim.x;
    for (; i < T3; i += stride) {
        if (i < T0) {
            pidx3[i] = lower_bound_shift(keys2, N2, keys3[i] >> 2);
        } else if (i < T1) {
            int k = i - T0;
            pidx2[k] = lower_bound_shift(keys1, N1, keys2[k] >> 2);
        } else if (i < T2) {
            x7p[i - T1] = 0.0f;
        } else {
            x6p[i - T2] = 0.0f;
        }
    }
}

// segment-max pool. Post-ReLU values >= 0, so int-bit atomicMax == float max
// and 0-init matches the reference's (-inf -> 0) fill.
template <int C>
__global__ void pool_kernel(const float* __restrict__ child,
                            const int* __restrict__ pidx,
                            int Nc, int Np, float* __restrict__ parent) {
    int i = blockIdx.x * blockDim.x + threadIdx.x;
    if (i >= Nc * C) return;
    int node = i / C;
    int c = i - node * C;
    int p = pidx[node];
    if (p < Np) {
        float v = child[i];
        atomicMax(reinterpret_cast<int*>(&parent[(size_t)p * C + c]),
                  __float_as_int(v));
    }
}

// ---------------- fused gather + (9*CIN -> COB) conv, packed f32x2 -----------
// Full COUT per block (no duplicate gathers). Weight pairs staged once in
// dynamic shared as ws[(j*CIN+c)][o_pair]; inner loop: broadcast activation
// scalar into f32x2, LDS.128 two weight pairs, 2x ffma2. Packed accs give
// 2 lane-FMAs per fma-pipe slot. INDIRECT fuses the unpool gather.
template <int CIN, int COB, int NPN, bool RELU, bool INDIRECT>
__global__ void __launch_bounds__(128)
conv_kernel(const float* __restrict__ feat, const int* __restrict__ neigh,
            const int* __restrict__ pidx, int Nfeat, int ostride,
            const float* __restrict__ w, const float* __restrict__ b,
            float* __restrict__ out) {
    extern __shared__ __align__(16) char smem_raw[];
    const int tid = threadIdx.x;
    const int oc_base = blockIdx.y * COB;
    const int cin9 = 9 * CIN;

    int node[NPN];
    int idx[NPN][9];
#pragma unroll
    for (int t = 0; t < NPN; t++) {
        node[t] = blockIdx.x * (128 * NPN) + t * 128 + tid;
#pragma unroll
        for (int j = 0; j < 9; j++) idx[t][j] = neigh[(size_t)node[t] * 9 + j];
        if (INDIRECT) {
#pragma unroll
            for (int j = 0; j < 9; j++) {
                if (idx[t][j] >= 0) {
                    int p = pidx[idx[t][j]];
                    idx[t][j] = p < Nfeat ? p : Nfeat - 1;
                }
            }
        }
    }

    if constexpr (COB == 1) {
        // tiny head layer: scalar path, weights in shared as float
        float* ws = reinterpret_cast<float*>(smem_raw);
        for (int s = tid; s < cin9; s += 128)
            ws[s] = w[(size_t)oc_base * cin9 + s];
        __syncthreads();

        float acc[NPN];
#pragma unroll
        for (int t = 0; t < NPN; t++) acc[t] = b[oc_base];
        for (int j = 0; j < 9; j++) {
#pragma unroll
            for (int c4 = 0; c4 < CIN; c4 += 4) {
                float4 wv = *reinterpret_cast<const float4*>(&ws[j * CIN + c4]);
#pragma unroll
                for (int t = 0; t < NPN; t++) {
                    float4 f = (idx[t][j] >= 0)
                        ? *reinterpret_cast<const float4*>(
                              &feat[(size_t)idx[t][j] * CIN + c4])
                        : make_float4(0.f, 0.f, 0.f, 0.f);
                    acc[t] += f.x * wv.x + f.y * wv.y + f.z * wv.z + f.w * wv.w;
                }
            }
        }
#pragma unroll
        for (int t = 0; t < NPN; t++)
            out[(size_t)node[t] * ostride + oc_base] =
                RELU ? fmaxf(acc[t], 0.f) : acc[t];
    } else {
        constexpr int PAIRS = COB / 2;
        ull* ws = reinterpret_cast<ull*>(smem_raw);
        // ws[rc * PAIRS + o2] = pack(w[2*o2][rc], w[2*o2+1][rc]), rc = j*CIN+c
        for (int s = tid; s < cin9 * PAIRS; s += 128) {
            int rc = s / PAIRS;
            int o2 = s - rc * PAIRS;
            float lo = w[(size_t)(oc_base + 2 * o2) * cin9 + rc];
            float hi = w[(size_t)(oc_base + 2 * o2 + 1) * cin9 + rc];
            ws[s] = pack2(lo, hi);
        }
        __syncthreads();

        ull acc2[NPN][PAIRS];
#pragma unroll
        for (int o2 = 0; o2 < PAIRS; o2++) {
            ull bv = pack2(b[oc_base + 2 * o2], b[oc_base + 2 * o2 + 1]);
#pragma unroll
            for (int t = 0; t < NPN; t++) acc2[t][o2] = bv;
        }

        if constexpr (CIN == 1) {
#pragma unroll
            for (int j = 0; j < 9; j++) {
                ull ff[NPN];
#pragma unroll
                for (int t = 0; t < NPN; t++)
                    ff[t] = bcast2((idx[t][j] >= 0) ? __ldg(&feat[idx[t][j]])
                                                    : 0.f);
                const ull* wrow = ws + j * PAIRS;
#pragma unroll
                for (int og = 0; og < PAIRS; og += 2) {
                    ulonglong2 wl =
                        *reinterpret_cast<const ulonglong2*>(wrow + og);
#pragma unroll
                    for (int t = 0; t < NPN; t++) {
                        ffma2(acc2[t][og], ff[t], wl.x);
                        ffma2(acc2[t][og + 1], ff[t], wl.y);
                    }
                }
            }
        } else {
            for (int j = 0; j < 9; j++) {
#pragma unroll 2
                for (int c4 = 0; c4 < CIN; c4 += 4) {
                    float4 f[NPN];
#pragma unroll
                    for (int t = 0; t < NPN; t++) {
                        if (idx[t][j] >= 0)
                            f[t] = *reinterpret_cast<const float4*>(
                                &feat[(size_t)idx[t][j] * CIN + c4]);
                        else
                            f[t] = make_float4(0.f, 0.f, 0.f, 0.f);
                    }
#pragma unroll
                    for (int c = 0; c < 4; c++) {
                        ull ff[NPN];
#pragma unroll
                        for (int t = 0; t < NPN; t++) {
                            float fv = c == 0 ? f[t].x : c == 1 ? f[t].y
                                     : c == 2 ? f[t].z : f[t].w;
                            ff[t] = bcast2(fv);
                        }
                        const ull* wrow = ws + (j * CIN + c4 + c) * PAIRS;
#pragma unroll
                        for (int og = 0; og < PAIRS; og += 2) {
                            ulonglong2 wl =
                                *reinterpret_cast<const ulonglong2*>(wrow + og);
#pragma unroll
                            for (int t = 0; t < NPN; t++) {
                                ffma2(acc2[t][og], ff[t], wl.x);
                                ffma2(acc2[t][og + 1], ff[t], wl.y);
                            }
                        }
                    }
                }
            }
        }

#pragma unroll
        for (int t = 0; t < NPN; t++) {
            float* orow = out + (size_t)node[t] * ostride + oc_base;
#pragma unroll
            for (int o = 0; o < COB; o += 4) {
                float2 p0 = unpack2(acc2[t][o / 2]);
                float2 p1 = unpack2(acc2[t][o / 2 + 1]);
                float4 v;
                v.x = RELU ? fmaxf(p0.x, 0.f) : p0.x;
                v.y = RELU ? fmaxf(p0.y, 0.f) : p0.y;
                v.z = RELU ? fmaxf(p1.x, 0.f) : p1.x;
                v.w = RELU ? fmaxf(p1.y, 0.f) : p1.y;
                *reinterpret_cast<float4*>(orow + o) = v;
            }
        }
    }
}

// ---------------- launch ------------------------------------------------------
static inline int cdiv(int a, int b) { return (a + b - 1) / b; }

extern "C" void kernel_launch(void* const* d_in, const int* in_sizes, int n_in,
                              void* d_out, int out_size) {
    const float* features = (const float*)d_in[0];
    const int* keys3   = (const int*)d_in[1];
    const int* keys2   = (const int*)d_in[2];
    const int* keys1   = (const int*)d_in[3];
    const int* neighs3 = (const int*)d_in[4];
    const int* neighs2 = (const int*)d_in[5];
    const int* neighs1 = (const int*)d_in[6];
    const float* w_enc1 = (const float*)d_in[7];
    const float* b_enc1 = (const float*)d_in[8];
    const float* w_enc2 = (const float*)d_in[9];
    const float* b_enc2 = (const float*)d_in[10];
    const float* w_enc3 = (const float*)d_in[11];
    const float* b_enc3 = (const float*)d_in[12];
    const float* w_dec1 = (const float*)d_in[13];
    const float* b_dec1 = (const float*)d_in[14];
    const float* w_dec2 = (const float*)d_in[15];
    const float* b_dec2 = (const float*)d_in[16];
    const float* w_head = (const float*)d_in[17];
    const float* b_head = (const float*)d_in[18];
    float* out = (float*)d_out;

    float *x8, *x7p, *x7, *x6p, *x6, *x7dec, *x8dec;
    int *pidx3, *pidx2;
    cudaGetSymbolAddress((void**)&x8, g_x8);
    cudaGetSymbolAddress((void**)&x7p, g_x7p);
    cudaGetSymbolAddress((void**)&x7, g_x7);
    cudaGetSymbolAddress((void**)&x6p, g_x6p);
    cudaGetSymbolAddress((void**)&x6, g_x6);
    cudaGetSymbolAddress((void**)&x7dec, g_x7dec);
    cudaGetSymbolAddress((void**)&x8dec, g_x8dec);
    cudaGetSymbolAddress((void**)&pidx3, g_pidx3);
    cudaGetSymbolAddress((void**)&pidx2, g_pidx2);

    // dec1 needs 72KB dynamic smem (full COUT=32, CIN=64 slab)
    cudaFuncSetAttribute((const void*)conv_kernel<64, 32, 1, true, true>,
                         cudaFuncAttributeMaxDynamicSharedMemorySize, 73728);

    // 0: fused prep (pidx3, pidx2, zero pool accumulators)
    prep_kernel<<<2048, 256>>>(keys3, keys2, keys1, pidx3, pidx2, x7p, x6p);

    // 1: enc1 [N3,1]->[N3,16]  smem = 9*1*8 pairs *8B = 576B
    conv_kernel<1, 16, 2, true, false><<<dim3(N3 / 256, 1), 128, 576>>>(
        features, neighs3, nullptr, N3, 16, w_enc1, b_enc1, x8);
    // 2: pool 3->2
    pool_kernel<16><<<cdiv(N3 * 16, 256), 256>>>(x8, pidx3, N3, N2, x7p);
    // 3: enc2 [N2,16]->[N2,32]  full COUT, smem 18432B
    conv_kernel<16, 32, 1, true, false><<<dim3(N2 / 128, 1), 128, 18432>>>(
        x7p, neighs2, nullptr, N2, 32, w_enc2, b_enc2, x7);
    // 4: pool 2->1
    pool_kernel<32><<<cdiv(N2 * 32, 256), 256>>>(x7, pidx2, N2, N1, x6p);
    // 5: enc3 [N1,32]->[N1,64]  y=2 split for grid fill, smem 36864B
    conv_kernel<32, 32, 1, true, false><<<dim3(N1 / 128, 2), 128, 36864>>>(
        x6p, neighs1, nullptr, N1, 64, w_enc3, b_enc3, x6);
    // 6: dec1 (unpool 1->2 fused) [N2,9*64]->[N2,32]  full COUT, smem 73728B
    conv_kernel<64, 32, 1, true, true><<<dim3(N2 / 128, 1), 128, 73728>>>(
        x6, neighs2, pidx2, N1, 32, w_dec1, b_dec1, x7dec);
    // 7: dec2 (unpool 2->3 fused) [N3,9*32]->[N3,16]  full COUT, smem 18432B
    conv_kernel<32, 16, 2, true, true><<<dim3(N3 / 256, 1), 128, 18432>>>(
        x7dec, neighs3, pidx3, N2, 16, w_dec2, b_dec2, x8dec);
    // 8: head [N3,16]->[N3,1], no relu, smem 576B
    conv_kernel<16, 1, 4, false, false><<<dim3(N3 / 512, 1), 128, 576>>>(
        x8dec, neighs3, nullptr, N3, 1, w_head, b_head, out);
}